// round 7
// baseline (speedup 1.0000x reference)
#include <cuda_runtime.h>

// Problem constants (fixed by the dataset)
#define NA 250000
#define NB 500000
#define NG 50000
#define DD 64
#define EA 1000000
#define EG 500000

// Output layout (float offsets): [atom_ft | ft(NB x 320) | global_ft]
#define OFF_FT  (NA * DD)                 // 16,000,000
#define OFF_GL  (OFF_FT + NB * 320)       // 176,000,000

#define ATOM_F4 (NA * 16)                 // 4,000,000
#define GLOB_F4 (NG * 16)                 //   800,000

// Per-destination edge bins (atomic bump allocation). Degrees ~Poisson(2)/(1);
// capacities astronomically safe; clamped anyway.
#define CAP_A 48
#define CAP_G 32

// Counts are zero-initialized at module load; the reduce kernel re-zeros them
// after reading, so every kernel_launch call sees zeros (deterministic).
__device__ int g_cnt_a[NB];
__device__ int g_cnt_g[NB];
__device__ int g_bin_a[(long long)NB * CAP_A];
__device__ int g_bin_g[(long long)NB * CAP_G];

// ---------------------------------------------------------------------------
// Kernel 1: edge binning (latency-bound spread atomics), both edge sets.
// ---------------------------------------------------------------------------
__global__ void __launch_bounds__(256)
scatter_kernel(const int* __restrict__ a_src,
               const int* __restrict__ a_dst,
               const int* __restrict__ g_src,
               const int* __restrict__ g_dst) {
    int e = blockIdx.x * blockDim.x + threadIdx.x;
    if (e < EA) {
        int s = a_src[e];
        int d = a_dst[e];
        int pos = atomicAdd(g_cnt_a + d, 1);
        if (pos < CAP_A) g_bin_a[(long long)d * CAP_A + pos] = s;
    } else {
        int eg = e - EA;
        if (eg < EG) {
            int s = g_src[eg];
            int d = g_dst[eg];
            int pos = atomicAdd(g_cnt_g + d, 1);
            if (pos < CAP_G) g_bin_g[(long long)d * CAP_G + pos] = s;
        }
    }
}

// ---------------------------------------------------------------------------
// Kernel 2: fused passthrough copies + per-bond gather-reduce + counter reset.
// 16 lanes per bond row; each thread additionally copies <=1 float4 of the
// atom/global passthrough (independent streaming work in every wave).
// ---------------------------------------------------------------------------
#define ACCA(v)                                                         \
    do {                                                                \
        sa.x += (v).x; sa.y += (v).y; sa.z += (v).z; sa.w += (v).w;     \
        ma.x = fmaxf(ma.x, (v).x); ma.y = fmaxf(ma.y, (v).y);           \
        ma.z = fmaxf(ma.z, (v).z); ma.w = fmaxf(ma.w, (v).w);           \
    } while (0)
#define ACCG(v)                                                         \
    do {                                                                \
        sg.x += (v).x; sg.y += (v).y; sg.z += (v).z; sg.w += (v).w;     \
        mg.x = fmaxf(mg.x, (v).x); mg.y = fmaxf(mg.y, (v).y);           \
        mg.z = fmaxf(mg.z, (v).z); mg.w = fmaxf(mg.w, (v).w);           \
    } while (0)

__global__ void __launch_bounds__(256)
fused_kernel(const float4* __restrict__ bond4,
             const float4* __restrict__ atom4,
             const float4* __restrict__ glob4,
             float4* __restrict__ out4) {
    // NB*16 == 8,000,000, exact multiple of 256: no tail, no divergence.
    int t    = blockIdx.x * 256 + threadIdx.x;
    int row  = t >> 4;
    int lane = t & 15;

    // --- independent passthrough copy slice (streaming, hides gather latency)
    if (t < ATOM_F4) {
        __stcs(out4 + t, __ldg(atom4 + t));
    } else if (t < ATOM_F4 + GLOB_F4) {
        int j = t - ATOM_F4;
        __stcs(out4 + (OFF_GL / 4) + j, __ldg(glob4 + j));
    }

    // --- degrees: plain broadcast load by all lanes; lane 0 resets AFTER the
    // loads (warp program order => race-free; each row owned by one group).
    int da = g_cnt_a[row];
    int dg = g_cnt_g[row];
    if (lane == 0) { g_cnt_a[row] = 0; g_cnt_g[row] = 0; }
    if (da > CAP_A) da = CAP_A;
    if (dg > CAP_G) dg = CAP_G;

    const int4* __restrict__ binA = (const int4*)(g_bin_a + (long long)row * CAP_A);
    const int4* __restrict__ binG = (const int4*)(g_bin_g + (long long)row * CAP_G);

    // Front-batched independent loads: bond row + both first index vectors.
    float4 bv = __ldcs(bond4 + (long long)row * 16 + lane);
    int4 ia = __ldg(binA);   // memory always valid; values used only when in-degree
    int4 ig = __ldg(binG);

    float4* __restrict__ orow = out4 + (OFF_FT / 4) + (long long)row * 80;
    __stcs(orow + lane, bv);                       // bond passthrough

    const float NINF = __int_as_float(0xFF800000);
    float4 sa = make_float4(0.f, 0.f, 0.f, 0.f);
    float4 ma = make_float4(NINF, NINF, NINF, NINF);
    float4 sg = make_float4(0.f, 0.f, 0.f, 0.f);
    float4 mg = make_float4(NINF, NINF, NINF, NINF);

    // First batch, A and G interleaved. Out-of-degree gather addresses clamp
    // to the first index -> duplicate line, coalesces free; ACC predicated.
    {
        int a1 = (da > 1) ? ia.y : ia.x;
        int a2 = (da > 2) ? ia.z : ia.x;
        int a3 = (da > 3) ? ia.w : ia.x;
        int g1 = (dg > 1) ? ig.y : ig.x;
        int g2 = (dg > 2) ? ig.z : ig.x;
        int g3 = (dg > 3) ? ig.w : ig.x;
        if (da > 0) {
            float4 v0 = __ldg(atom4 + (long long)ia.x * 16 + lane);
            float4 v1 = __ldg(atom4 + (long long)a1 * 16 + lane);
            float4 v2 = __ldg(atom4 + (long long)a2 * 16 + lane);
            float4 v3 = __ldg(atom4 + (long long)a3 * 16 + lane);
            ACCA(v0);
            if (da > 1) ACCA(v1);
            if (da > 2) ACCA(v2);
            if (da > 3) ACCA(v3);
        }
        if (dg > 0) {
            float4 v0 = __ldg(glob4 + (long long)ig.x * 16 + lane);
            float4 v1 = __ldg(glob4 + (long long)g1 * 16 + lane);
            float4 v2 = __ldg(glob4 + (long long)g2 * 16 + lane);
            float4 v3 = __ldg(glob4 + (long long)g3 * 16 + lane);
            ACCG(v0);
            if (dg > 1) ACCG(v1);
            if (dg > 2) ACCG(v2);
            if (dg > 3) ACCG(v3);
        }
    }

    // Rare tails (deg > 4): ~5% of A rows, ~0.4% of G rows.
    #pragma unroll 1
    for (int j = 4; j < da; j += 4) {
        int4 ix = __ldg(binA + (j >> 2));
        int i1 = (j + 1 < da) ? ix.y : ix.x;
        int i2 = (j + 2 < da) ? ix.z : ix.x;
        int i3 = (j + 3 < da) ? ix.w : ix.x;
        float4 v0 = __ldg(atom4 + (long long)ix.x * 16 + lane);
        float4 v1 = __ldg(atom4 + (long long)i1 * 16 + lane);
        float4 v2 = __ldg(atom4 + (long long)i2 * 16 + lane);
        float4 v3 = __ldg(atom4 + (long long)i3 * 16 + lane);
        ACCA(v0);
        if (j + 1 < da) ACCA(v1);
        if (j + 2 < da) ACCA(v2);
        if (j + 3 < da) ACCA(v3);
    }
    #pragma unroll 1
    for (int j = 4; j < dg; j += 4) {
        int4 ix = __ldg(binG + (j >> 2));
        int i1 = (j + 1 < dg) ? ix.y : ix.x;
        int i2 = (j + 2 < dg) ? ix.z : ix.x;
        int i3 = (j + 3 < dg) ? ix.w : ix.x;
        float4 v0 = __ldg(glob4 + (long long)ix.x * 16 + lane);
        float4 v1 = __ldg(glob4 + (long long)i1 * 16 + lane);
        float4 v2 = __ldg(glob4 + (long long)i2 * 16 + lane);
        float4 v3 = __ldg(glob4 + (long long)i3 * 16 + lane);
        ACCG(v0);
        if (j + 1 < dg) ACCG(v1);
        if (j + 2 < dg) ACCG(v2);
        if (j + 3 < dg) ACCG(v3);
    }

    float inva = 1.0f / (float)(da > 1 ? da : 1);
    float invg = 1.0f / (float)(dg > 1 ? dg : 1);
    __stcs(orow + 16 + lane, make_float4(sa.x * inva, sa.y * inva,
                                         sa.z * inva, sa.w * inva));
    __stcs(orow + 32 + lane, da ? ma : make_float4(0.f, 0.f, 0.f, 0.f));
    __stcs(orow + 48 + lane, make_float4(sg.x * invg, sg.y * invg,
                                         sg.z * invg, sg.w * invg));
    __stcs(orow + 64 + lane, dg ? mg : make_float4(0.f, 0.f, 0.f, 0.f));
}

extern "C" void kernel_launch(void* const* d_in, const int* in_sizes, int n_in,
                              void* d_out, int out_size) {
    const float4* atom4   = (const float4*)d_in[0];
    const float4* bond4   = (const float4*)d_in[1];
    const float4* glob4   = (const float4*)d_in[2];
    const int*    a2b_src = (const int*)d_in[3];
    const int*    a2b_dst = (const int*)d_in[4];
    const int*    g2b_src = (const int*)d_in[5];
    const int*    g2b_dst = (const int*)d_in[6];
    float* out = (float*)d_out;

    scatter_kernel<<<(EA + EG + 255) / 256, 256>>>(a2b_src, a2b_dst,
                                                   g2b_src, g2b_dst);

    int blocks = (int)(((long long)NB * 16) / 256);   // 31250
    fused_kernel<<<blocks, 256>>>(bond4, atom4, glob4, (float4*)out);
}

// round 8
// speedup vs baseline: 2.8028x; 2.8028x over previous
#include <cuda_runtime.h>

// Problem constants (fixed by the dataset)
#define NA 250000
#define NB 500000
#define NG 50000
#define DD 64
#define EA 1000000
#define EG 500000

// Output layout (float offsets): [atom_ft | ft(NB x 320) | global_ft]
#define OFF_FT  (NA * DD)                 // 16,000,000
#define OFF_GL  (OFF_FT + NB * 320)       // 176,000,000

// Per-destination edge bins (atomic bump allocation). Degrees ~Poisson(2)/(1);
// capacities astronomically safe; clamped anyway.
#define CAP_A 48
#define CAP_G 32

__device__ int g_cnt_a[NB];
__device__ int g_cnt_g[NB];
__device__ int g_bin_a[(long long)NB * CAP_A];
__device__ int g_bin_g[(long long)NB * CAP_G];

__global__ void __launch_bounds__(256)
zero_cnt_kernel() {
    int i = blockIdx.x * blockDim.x + threadIdx.x;
    if (i < NB) { g_cnt_a[i] = 0; g_cnt_g[i] = 0; }
}

// Both edge sets in one launch (latency-bound spread atomics).
__global__ void __launch_bounds__(256)
scatter_kernel(const int* __restrict__ a_src,
               const int* __restrict__ a_dst,
               const int* __restrict__ g_src,
               const int* __restrict__ g_dst) {
    int e = blockIdx.x * blockDim.x + threadIdx.x;
    if (e < EA) {
        int s = a_src[e];
        int d = a_dst[e];
        int pos = atomicAdd(g_cnt_a + d, 1);
        if (pos < CAP_A) g_bin_a[(long long)d * CAP_A + pos] = s;
    } else {
        int eg = e - EA;
        if (eg < EG) {
            int s = g_src[eg];
            int d = g_dst[eg];
            int pos = atomicAdd(g_cnt_g + d, 1);
            if (pos < CAP_G) g_bin_g[(long long)d * CAP_G + pos] = s;
        }
    }
}

#define ACCA(v)                                                         \
    do {                                                                \
        sa.x += (v).x; sa.y += (v).y; sa.z += (v).z; sa.w += (v).w;     \
        ma.x = fmaxf(ma.x, (v).x); ma.y = fmaxf(ma.y, (v).y);           \
        ma.z = fmaxf(ma.z, (v).z); ma.w = fmaxf(ma.w, (v).w);           \
    } while (0)
#define ACCG(v)                                                         \
    do {                                                                \
        sg.x += (v).x; sg.y += (v).y; sg.z += (v).z; sg.w += (v).w;     \
        mg.x = fmaxf(mg.x, (v).x); mg.y = fmaxf(mg.y, (v).y);           \
        mg.z = fmaxf(mg.z, (v).z); mg.w = fmaxf(mg.w, (v).w);           \
    } while (0)

// Fused kernel: 50000 blocks total. Every group of 8 consecutive block ids
// contains 3 copy blocks + 5 reduce blocks (exact: 6250 groups; 6250*3=18750
// copy blocks cover atom+global passthrough, 6250*5=31250 reduce blocks cover
// NB rows at 16 lanes/row). Streaming copies and latency-bound gathers
// coexist in every wave, keeping DRAM fed.
#define COPY_BLOCKS   18750
#define REDUCE_BLOCKS 31250

__global__ void __launch_bounds__(256)
fused_kernel(const float4* __restrict__ bond4,
             const float4* __restrict__ atom4,
             const float4* __restrict__ glob4,
             float4* __restrict__ out4) {
    int b   = blockIdx.x;
    int grp = b >> 3;
    int sub = b & 7;

    if (sub < 3) {
        // ---- copy block ----
        int cb = grp * 3 + sub;                 // 0 .. 18749
        int i  = cb * 256 + threadIdx.x;
        if (i < NA * 16) {
            __stcs(out4 + i, __ldg(atom4 + i)); // pre-warms L2 with atom table
        } else {
            int j = i - NA * 16;
            __stcs(out4 + (OFF_GL / 4) + j, __ldg(glob4 + j));
        }
        return;
    }

    // ---- reduce block ----
    int rb   = grp * 5 + (sub - 3);             // 0 .. 31249
    int t    = rb * 256 + threadIdx.x;          // NB*16 exact multiple of 256
    int row  = t >> 4;
    int lane = t & 15;

    // Uniform broadcast loads: all 16 lanes read the same counter word.
    int da = __ldg(g_cnt_a + row); if (da > CAP_A) da = CAP_A;
    int dg = __ldg(g_cnt_g + row); if (dg > CAP_G) dg = CAP_G;

    const int4* __restrict__ binA = (const int4*)(g_bin_a + (long long)row * CAP_A);
    const int4* __restrict__ binG = (const int4*)(g_bin_g + (long long)row * CAP_G);

    // Front-batched independent loads: bond row + both first index vectors.
    float4 bv = __ldcs(bond4 + (long long)row * 16 + lane);
    int4 ia = __ldg(binA);
    int4 ig = __ldg(binG);

    float4* __restrict__ orow = out4 + (OFF_FT / 4) + (long long)row * 80;
    __stcs(orow + lane, bv);                    // bond passthrough

    const float NINF = __int_as_float(0xFF800000);
    float4 sa = make_float4(0.f, 0.f, 0.f, 0.f);
    float4 ma = make_float4(NINF, NINF, NINF, NINF);
    float4 sg = make_float4(0.f, 0.f, 0.f, 0.f);
    float4 mg = make_float4(NINF, NINF, NINF, NINF);

    // First batch, A and G interleaved. Out-of-degree gather addresses clamp
    // to the first index (duplicate line, coalesces free); ACC predicated.
    {
        int a1 = (da > 1) ? ia.y : ia.x;
        int a2 = (da > 2) ? ia.z : ia.x;
        int a3 = (da > 3) ? ia.w : ia.x;
        int g1 = (dg > 1) ? ig.y : ig.x;
        int g2 = (dg > 2) ? ig.z : ig.x;
        int g3 = (dg > 3) ? ig.w : ig.x;
        if (da > 0) {
            float4 v0 = __ldg(atom4 + (long long)ia.x * 16 + lane);
            float4 v1 = __ldg(atom4 + (long long)a1 * 16 + lane);
            float4 v2 = __ldg(atom4 + (long long)a2 * 16 + lane);
            float4 v3 = __ldg(atom4 + (long long)a3 * 16 + lane);
            ACCA(v0);
            if (da > 1) ACCA(v1);
            if (da > 2) ACCA(v2);
            if (da > 3) ACCA(v3);
        }
        if (dg > 0) {
            float4 v0 = __ldg(glob4 + (long long)ig.x * 16 + lane);
            float4 v1 = __ldg(glob4 + (long long)g1 * 16 + lane);
            float4 v2 = __ldg(glob4 + (long long)g2 * 16 + lane);
            float4 v3 = __ldg(glob4 + (long long)g3 * 16 + lane);
            ACCG(v0);
            if (dg > 1) ACCG(v1);
            if (dg > 2) ACCG(v2);
            if (dg > 3) ACCG(v3);
        }
    }

    // Rare tails (deg > 4): ~5% of A rows, ~0.4% of G rows.
    #pragma unroll 1
    for (int j = 4; j < da; j += 4) {
        int4 ix = __ldg(binA + (j >> 2));
        int i1 = (j + 1 < da) ? ix.y : ix.x;
        int i2 = (j + 2 < da) ? ix.z : ix.x;
        int i3 = (j + 3 < da) ? ix.w : ix.x;
        float4 v0 = __ldg(atom4 + (long long)ix.x * 16 + lane);
        float4 v1 = __ldg(atom4 + (long long)i1 * 16 + lane);
        float4 v2 = __ldg(atom4 + (long long)i2 * 16 + lane);
        float4 v3 = __ldg(atom4 + (long long)i3 * 16 + lane);
        ACCA(v0);
        if (j + 1 < da) ACCA(v1);
        if (j + 2 < da) ACCA(v2);
        if (j + 3 < da) ACCA(v3);
    }
    #pragma unroll 1
    for (int j = 4; j < dg; j += 4) {
        int4 ix = __ldg(binG + (j >> 2));
        int i1 = (j + 1 < dg) ? ix.y : ix.x;
        int i2 = (j + 2 < dg) ? ix.z : ix.x;
        int i3 = (j + 3 < dg) ? ix.w : ix.x;
        float4 v0 = __ldg(glob4 + (long long)ix.x * 16 + lane);
        float4 v1 = __ldg(glob4 + (long long)i1 * 16 + lane);
        float4 v2 = __ldg(glob4 + (long long)i2 * 16 + lane);
        float4 v3 = __ldg(glob4 + (long long)i3 * 16 + lane);
        ACCG(v0);
        if (j + 1 < dg) ACCG(v1);
        if (j + 2 < dg) ACCG(v2);
        if (j + 3 < dg) ACCG(v3);
    }

    float inva = 1.0f / (float)(da > 1 ? da : 1);
    float invg = 1.0f / (float)(dg > 1 ? dg : 1);
    __stcs(orow + 16 + lane, make_float4(sa.x * inva, sa.y * inva,
                                         sa.z * inva, sa.w * inva));
    __stcs(orow + 32 + lane, da ? ma : make_float4(0.f, 0.f, 0.f, 0.f));
    __stcs(orow + 48 + lane, make_float4(sg.x * invg, sg.y * invg,
                                         sg.z * invg, sg.w * invg));
    __stcs(orow + 64 + lane, dg ? mg : make_float4(0.f, 0.f, 0.f, 0.f));
}

extern "C" void kernel_launch(void* const* d_in, const int* in_sizes, int n_in,
                              void* d_out, int out_size) {
    const float4* atom4   = (const float4*)d_in[0];
    const float4* bond4   = (const float4*)d_in[1];
    const float4* glob4   = (const float4*)d_in[2];
    const int*    a2b_src = (const int*)d_in[3];
    const int*    a2b_dst = (const int*)d_in[4];
    const int*    g2b_src = (const int*)d_in[5];
    const int*    g2b_dst = (const int*)d_in[6];
    float* out = (float*)d_out;

    zero_cnt_kernel<<<(NB + 255) / 256, 256>>>();

    scatter_kernel<<<(EA + EG + 255) / 256, 256>>>(a2b_src, a2b_dst,
                                                   g2b_src, g2b_dst);

    fused_kernel<<<COPY_BLOCKS + REDUCE_BLOCKS, 256>>>(bond4, atom4, glob4,
                                                       (float4*)out);
}

// round 9
// speedup vs baseline: 3.2870x; 1.1728x over previous
#include <cuda_runtime.h>

// Problem constants (fixed by the dataset)
#define NA 250000
#define NB 500000
#define NG 50000
#define DD 64
#define EA 1000000
#define EG 500000

// Output layout (float offsets): [atom_ft | ft(NB x 320) | global_ft]
#define OFF_FT  (NA * DD)                 // 16,000,000
#define OFF_GL  (OFF_FT + NB * 320)       // 176,000,000

// Per-destination edge bins (atomic bump allocation). Degrees ~Poisson(2)/(1)
// over 500k rows: expected max ~12 / ~9. CAP=16 keeps margin while shrinking
// the bin arrays to 32MB each (L2 residency for the gather tables).
#define CAP_A 16
#define CAP_G 16

__device__ int g_cnt_a[NB];
__device__ int g_cnt_g[NB];
__device__ int g_bin_a[(long long)NB * CAP_A];
__device__ int g_bin_g[(long long)NB * CAP_G];

__global__ void __launch_bounds__(256)
zero_cnt_kernel() {
    int i = blockIdx.x * blockDim.x + threadIdx.x;
    if (i < NB) { g_cnt_a[i] = 0; g_cnt_g[i] = 0; }
}

// Vectorized edge binning: 4 edges per thread via int4 (EA, EG divisible by 4).
// 8 independent atomics in flight per thread.
#define EA4 (EA / 4)   // 250000
#define EG4 (EG / 4)   // 125000
__global__ void __launch_bounds__(256)
scatter_kernel(const int4* __restrict__ a_src,
               const int4* __restrict__ a_dst,
               const int4* __restrict__ g_src,
               const int4* __restrict__ g_dst) {
    int t = blockIdx.x * blockDim.x + threadIdx.x;
    if (t < EA4) {
        int4 s = __ldg(a_src + t);
        int4 d = __ldg(a_dst + t);
        int p0 = atomicAdd(g_cnt_a + d.x, 1);
        int p1 = atomicAdd(g_cnt_a + d.y, 1);
        int p2 = atomicAdd(g_cnt_a + d.z, 1);
        int p3 = atomicAdd(g_cnt_a + d.w, 1);
        if (p0 < CAP_A) g_bin_a[(long long)d.x * CAP_A + p0] = s.x;
        if (p1 < CAP_A) g_bin_a[(long long)d.y * CAP_A + p1] = s.y;
        if (p2 < CAP_A) g_bin_a[(long long)d.z * CAP_A + p2] = s.z;
        if (p3 < CAP_A) g_bin_a[(long long)d.w * CAP_A + p3] = s.w;
    } else {
        int u = t - EA4;
        if (u < EG4) {
            int4 s = __ldg(g_src + u);
            int4 d = __ldg(g_dst + u);
            int p0 = atomicAdd(g_cnt_g + d.x, 1);
            int p1 = atomicAdd(g_cnt_g + d.y, 1);
            int p2 = atomicAdd(g_cnt_g + d.z, 1);
            int p3 = atomicAdd(g_cnt_g + d.w, 1);
            if (p0 < CAP_G) g_bin_g[(long long)d.x * CAP_G + p0] = s.x;
            if (p1 < CAP_G) g_bin_g[(long long)d.y * CAP_G + p1] = s.y;
            if (p2 < CAP_G) g_bin_g[(long long)d.z * CAP_G + p2] = s.z;
            if (p3 < CAP_G) g_bin_g[(long long)d.w * CAP_G + p3] = s.w;
        }
    }
}

#define ACC(v)                                                     \
    do {                                                           \
        s.x += (v).x; s.y += (v).y; s.z += (v).z; s.w += (v).w;    \
        m.x = fmaxf(m.x, (v).x); m.y = fmaxf(m.y, (v).y);          \
        m.z = fmaxf(m.z, (v).z); m.w = fmaxf(m.w, (v).w);          \
    } while (0)

// Unrolled-by-4 gather-reduce (R3-proven form): clamped indices -> all 4
// feature loads unconditional (MLP=4), accumulation predicated; deg==0 rows
// skip the loop entirely.
__device__ __forceinline__ void gather_reduce(const int* __restrict__ bin,
                                              const float4* __restrict__ tab,
                                              int deg, int lane,
                                              float4* __restrict__ o_mean,
                                              float4* __restrict__ o_max) {
    const float NINF = __int_as_float(0xFF800000);
    float4 s = make_float4(0.f, 0.f, 0.f, 0.f);
    float4 m = make_float4(NINF, NINF, NINF, NINF);

    #pragma unroll 1
    for (int j = 0; j < deg; j += 4) {
        int last = deg - 1;
        int i0 = __ldg(bin + j);
        int i1 = __ldg(bin + (j + 1 <= last ? j + 1 : last));
        int i2 = __ldg(bin + (j + 2 <= last ? j + 2 : last));
        int i3 = __ldg(bin + (j + 3 <= last ? j + 3 : last));
        float4 v0 = __ldg(tab + (long long)i0 * 16 + lane);
        float4 v1 = __ldg(tab + (long long)i1 * 16 + lane);
        float4 v2 = __ldg(tab + (long long)i2 * 16 + lane);
        float4 v3 = __ldg(tab + (long long)i3 * 16 + lane);
        ACC(v0);
        if (j + 1 < deg) ACC(v1);
        if (j + 2 < deg) ACC(v2);
        if (j + 3 < deg) ACC(v3);
    }
    float inv = 1.0f / (float)(deg > 1 ? deg : 1);
    __stcs(o_mean, make_float4(s.x * inv, s.y * inv, s.z * inv, s.w * inv));
    __stcs(o_max, deg ? m : make_float4(0.f, 0.f, 0.f, 0.f));
}

// Fused: passthrough copies as LEADING blocks (pre-warm L2 with the atom
// table before reduce waves start), then per-bond gather-reduce.
#define COPY_BLOCKS ((NA * 16 + NG * 16) / 256)   // 18750
__global__ void __launch_bounds__(256)
fused_kernel(const float4* __restrict__ bond4,
             const float4* __restrict__ atom4,
             const float4* __restrict__ glob4,
             float4* __restrict__ out4) {
    int b = blockIdx.x;
    if (b < COPY_BLOCKS) {
        int i = b * 256 + threadIdx.x;
        if (i < NA * 16) {
            __stcs(out4 + i, __ldg(atom4 + i));   // pre-warms L2 with atom table
        } else {
            int j = i - NA * 16;
            __stcs(out4 + (OFF_GL / 4) + j, __ldg(glob4 + j));
        }
        return;
    }

    // NB*16 == 8,000,000 is an exact multiple of 256: no tail, no divergence.
    long long t = (long long)(b - COPY_BLOCKS) * 256 + threadIdx.x;
    int row  = (int)(t >> 4);
    int lane = (int)(t & 15);

    // Uniform broadcast loads: all 16 lanes read the same counter word.
    int da = g_cnt_a[row]; if (da > CAP_A) da = CAP_A;
    int dg = g_cnt_g[row]; if (dg > CAP_G) dg = CAP_G;

    float4 bv = __ldcs(bond4 + (long long)row * 16 + lane);

    float4* __restrict__ orow = out4 + (OFF_FT / 4) + (long long)row * 80;
    __stcs(orow + lane, bv);                       // bond passthrough

    gather_reduce(g_bin_a + (long long)row * CAP_A, atom4, da, lane,
                  orow + 16 + lane, orow + 32 + lane);
    gather_reduce(g_bin_g + (long long)row * CAP_G, glob4, dg, lane,
                  orow + 48 + lane, orow + 64 + lane);
}

extern "C" void kernel_launch(void* const* d_in, const int* in_sizes, int n_in,
                              void* d_out, int out_size) {
    const float4* atom4   = (const float4*)d_in[0];
    const float4* bond4   = (const float4*)d_in[1];
    const float4* glob4   = (const float4*)d_in[2];
    const int*    a2b_src = (const int*)d_in[3];
    const int*    a2b_dst = (const int*)d_in[4];
    const int*    g2b_src = (const int*)d_in[5];
    const int*    g2b_dst = (const int*)d_in[6];
    float* out = (float*)d_out;

    zero_cnt_kernel<<<(NB + 255) / 256, 256>>>();

    scatter_kernel<<<(EA4 + EG4 + 255) / 256, 256>>>(
        (const int4*)a2b_src, (const int4*)a2b_dst,
        (const int4*)g2b_src, (const int4*)g2b_dst);

    int reduce_blocks = (int)(((long long)NB * 16) / 256);   // 31250
    fused_kernel<<<COPY_BLOCKS + reduce_blocks, 256>>>(bond4, atom4, glob4,
                                                       (float4*)out);
}